// round 4
// baseline (speedup 1.0000x reference)
#include <cuda_runtime.h>
#include <cstdint>
#include <cstdio>

// ---------------- problem dims ----------------
#define B8    8
#define N1    1024
#define DD    64
#define HH    4
#define DHH   16
#define DI    128
#define DS    64
#define ROWS  (B8*N1)          // 8192
#define BH    (B8*HH)          // 32
#define T1    1027             // conv1 output length
#define ROWS1 (B8*T1)          // 8216

// ---------------- scratch (static device globals; no allocation) ----------------
__device__ float g_xt   [ROWS*DD];
__device__ float g_wqkv [64*192];
__device__ float g_qkv  [ROWS*192];
__device__ float g_S    [33554432];     // (b,h,i,j) scores -> probs in place
__device__ float g_O    [ROWS*DD];      // attention output (b,i, h*16+d)
__device__ float g_attnp[ROWS*DD];
__device__ float g_x1   [ROWS*DD];
__device__ float g_xt2  [ROWS*DD];
__device__ float g_xz   [ROWS*256];
__device__ float g_u    [ROWS*DI];
__device__ float g_xdb  [ROWS*132];
__device__ float g_dt   [ROWS*DI];
__device__ float g_y    [ROWS*DI];
__device__ float g_ym   [ROWS*DI];
__device__ float g_mraw [ROWS*DD];
__device__ float g_mg   [ROWS*DD];
__device__ float g_B1   [256*512];
__device__ float g_A1   [ROWS1*256];
__device__ float g_xc1  [ROWS1*512];
__device__ float g_h1   [ROWS1*256];
__device__ float g_B2   [1024*64];
__device__ float g_A2   [ROWS*1024];
__device__ float g_ff   [ROWS*DD];
__device__ int   g_mask_mode;

// ---------------- helpers ----------------
__device__ __forceinline__ float fast_exp(float x) {
    // exp(x) via 2^t polynomial, FMA-pipe only (no MUFU). rel err ~3e-7.
    float t = x * 1.4426950408889634f;
    t = fminf(fmaxf(t, -126.0f), 126.0f);
    float fi = floorf(t);
    float f  = t - fi;
    float p = 0.0018775767f;
    p = fmaf(p, f, 0.0089893397f);
    p = fmaf(p, f, 0.055826318f);
    p = fmaf(p, f, 0.24015361f);
    p = fmaf(p, f, 0.69315308f);
    p = fmaf(p, f, 0.99999994f);
    return p * __int_as_float(((int)fi + 127) << 23);
}
__device__ __forceinline__ float sigmoid_f(float x) { return 1.0f / (1.0f + fast_exp(-x)); }
__device__ __forceinline__ float warp_sum(float v) {
    #pragma unroll
    for (int o = 16; o > 0; o >>= 1) v += __shfl_xor_sync(0xFFFFFFFFu, v, o);
    return v;
}

// ---------------- mask dtype sniffer ----------------
__global__ void maskmode_kernel(const unsigned int* __restrict__ m) {
    __shared__ int cf, co;
    if (threadIdx.x == 0) { cf = 0; co = 0; }
    __syncthreads();
    int lf = 0, lo = 0;
    for (int k = 0; k < 16; k++) {
        unsigned w = m[threadIdx.x + k * 256];
        if (w == 0x3F800000u) lf++;
        else if (w != 0u && w != 1u) lo++;
    }
    atomicAdd(&cf, lf); atomicAdd(&co, lo);
    __syncthreads();
    if (threadIdx.x == 0)
        g_mask_mode = (cf > 32) ? 0 : ((co > 32) ? 2 : 1);  // 0=f32, 1=i32, 2=u8
}

// ---------------- layernorm (warp per row of 64) ----------------
__global__ void ln_kernel(const float* __restrict__ x, const float* __restrict__ w,
                          const float* __restrict__ b, float* __restrict__ out, int rows) {
    int warp = (blockIdx.x * blockDim.x + threadIdx.x) >> 5;
    int lane = threadIdx.x & 31;
    if (warp >= rows) return;
    const float* xr = x + (size_t)warp * 64;
    float v0 = xr[lane], v1 = xr[lane + 32];
    float mean = warp_sum(v0 + v1) * (1.0f / 64.0f);
    float d0 = v0 - mean, d1 = v1 - mean;
    float var = warp_sum(d0 * d0 + d1 * d1) * (1.0f / 64.0f);
    float inv = rsqrtf(var + 1e-5f);
    float* orow = out + (size_t)warp * 64;
    orow[lane]      = d0 * inv * w[lane]      + b[lane];
    orow[lane + 32] = d1 * inv * w[lane + 32] + b[lane + 32];
}

// ---------------- generic GEMM: C[M,N] = A[M,K] * B[K,N] ----------------
__global__ void gemm_kernel(const float* __restrict__ A, const float* __restrict__ B,
                            float* __restrict__ C, int M, int N, int K) {
    __shared__ float As[16][68];
    __shared__ float Bs[16][68];
    int bm0 = blockIdx.y * 64, bn0 = blockIdx.x * 64;
    int tid = threadIdx.x;
    int tx = tid & 15, ty = tid >> 4;
    float acc[4][4] = {};
    for (int k0 = 0; k0 < K; k0 += 16) {
        #pragma unroll
        for (int i = 0; i < 4; i++) {
            int f = tid + i * 256;
            int m = f >> 4, kk = f & 15;
            int gm = bm0 + m, gk = k0 + kk;
            As[kk][m] = (gm < M && gk < K) ? A[(size_t)gm * K + gk] : 0.0f;
        }
        #pragma unroll
        for (int i = 0; i < 4; i++) {
            int f = tid + i * 256;
            int kk = f >> 6, n = f & 63;
            int gk = k0 + kk, gn = bn0 + n;
            Bs[kk][n] = (gk < K && gn < N) ? B[(size_t)gk * N + gn] : 0.0f;
        }
        __syncthreads();
        #pragma unroll
        for (int kk = 0; kk < 16; kk++) {
            float4 a = *(const float4*)&As[kk][ty * 4];
            float4 b4 = *(const float4*)&Bs[kk][tx * 4];
            float av[4] = {a.x, a.y, a.z, a.w};
            float bv[4] = {b4.x, b4.y, b4.z, b4.w};
            #pragma unroll
            for (int r = 0; r < 4; r++)
                #pragma unroll
                for (int c = 0; c < 4; c++)
                    acc[r][c] = fmaf(av[r], bv[c], acc[r][c]);
        }
        __syncthreads();
    }
    #pragma unroll
    for (int r = 0; r < 4; r++) {
        int gm = bm0 + ty * 4 + r;
        if (gm < M) {
            #pragma unroll
            for (int c = 0; c < 4; c++) {
                int gn = bn0 + tx * 4 + c;
                if (gn < N) C[(size_t)gm * N + gn] = acc[r][c];
            }
        }
    }
}

// ---------------- small builders ----------------
__global__ void build_wqkv(const float* __restrict__ Wq, const float* __restrict__ Wkv) {
    int idx = blockIdx.x * blockDim.x + threadIdx.x;
    if (idx >= 64 * 192) return;
    int k = idx / 192, c = idx % 192;
    g_wqkv[idx] = (c < 64) ? Wq[k * 64 + c] : Wkv[k * 128 + (c - 64)];
}
__global__ void build_b1(const float* __restrict__ c1w) {
    int idx = blockIdx.x * blockDim.x + threadIdx.x;
    if (idx >= 256 * 512) return;
    int r = idx >> 9, o = idx & 511;
    int kt = r >> 6, ci = r & 63;
    g_B1[idx] = c1w[o * 256 + ci * 4 + kt];
}
__global__ void build_b2(const float* __restrict__ d1w) {
    int idx = blockIdx.x * blockDim.x + threadIdx.x;
    if (idx >= 1024 * 64) return;
    int r = idx >> 6, co = idx & 63;
    int ci = r >> 2, j = r & 3;
    g_B2[idx] = d1w[ci * 256 + co * 4 + j];
}

// ---------------- attention scores: S = scale*(q.k + q.rel) + mask*(-1e12) ----------------
__global__ void attn_scores_kernel(const float* __restrict__ qkv,
                                   const float* __restrict__ relemb,
                                   const void* __restrict__ mask) {
    int jt = blockIdx.x, it = blockIdx.y, bh = blockIdx.z;
    int b = bh >> 2, h = bh & 3;
    int i0 = it * 64, j0 = jt * 64;
    __shared__ float q_sh[64][17];
    __shared__ float k_sh[64][17];
    __shared__ float rel_sh[127][17];
    int tid = threadIdx.x;
    const float* qbase = qkv + (size_t)(b * 1024 + i0) * 192 + h * 16;
    const float* kbase = qkv + (size_t)(b * 1024 + j0) * 192 + 64 + h * 16;
    for (int f = tid; f < 1024; f += 256) {
        int r = f >> 4, d = f & 15;
        q_sh[r][d] = qbase[r * 192 + d];
        k_sh[r][d] = kbase[r * 192 + d];
    }
    int pbase = i0 - j0 + 449;
    for (int f = tid; f < 127 * 16; f += 256) {
        int r = f >> 4, d = f & 15;
        int p = pbase + r;
        p = min(max(p, 0), 1024);
        rel_sh[r][d] = relemb[p * 16 + d];
    }
    __syncthreads();
    int tx = tid & 15, ty = tid >> 4;
    int lbase = (ty - tx) * 4 + 60;
    float acc[4][4] = {};
    #pragma unroll
    for (int d = 0; d < 16; d++) {
        float aq[4], bk[4], rl[7];
        #pragma unroll
        for (int r = 0; r < 4; r++) aq[r] = q_sh[ty * 4 + r][d];
        #pragma unroll
        for (int c = 0; c < 4; c++) bk[c] = k_sh[tx * 4 + c][d];
        #pragma unroll
        for (int m = 0; m < 7; m++) rl[m] = rel_sh[lbase + m][d];
        #pragma unroll
        for (int r = 0; r < 4; r++)
            #pragma unroll
            for (int c = 0; c < 4; c++)
                acc[r][c] = fmaf(aq[r], bk[c] + rl[r - c + 3], acc[r][c]);
    }
    int mode = g_mask_mode;
    size_t base = ((size_t)bh * 1024 + i0) * 1024 + j0;
    #pragma unroll
    for (int r = 0; r < 4; r++) {
        size_t rowo = base + (size_t)(ty * 4 + r) * 1024 + tx * 4;
        float4 out;
        #pragma unroll
        for (int c = 0; c < 4; c++) {
            float s = acc[r][c] * 0.25f;
            size_t mi = rowo + c;
            bool msk;
            if (mode == 0)      msk = ((const float*)mask)[mi] != 0.0f;
            else if (mode == 1) msk = ((const int*)mask)[mi] != 0;
            else                msk = ((const unsigned char*)mask)[mi] != 0;
            if (msk) s -= 1e12f;
            (&out.x)[c] = s;
        }
        *(float4*)(g_S + rowo) = out;
    }
}

// ---------------- row softmax over 1024 (poly exp) ----------------
__global__ void softmax_kernel(float* __restrict__ S) {
    size_t row = blockIdx.x;
    int tid = threadIdx.x;
    float* rp = S + row * 1024;
    float4 v = *(float4*)(rp + tid * 4);
    float m = fmaxf(fmaxf(v.x, v.y), fmaxf(v.z, v.w));
    __shared__ float s_max[8], s_sum[8];
    #pragma unroll
    for (int o = 16; o > 0; o >>= 1) m = fmaxf(m, __shfl_xor_sync(0xFFFFFFFFu, m, o));
    if ((tid & 31) == 0) s_max[tid >> 5] = m;
    __syncthreads();
    float mm = s_max[0];
    #pragma unroll
    for (int w = 1; w < 8; w++) mm = fmaxf(mm, s_max[w]);
    float4 e;
    e.x = fast_exp(v.x - mm); e.y = fast_exp(v.y - mm);
    e.z = fast_exp(v.z - mm); e.w = fast_exp(v.w - mm);
    float s = e.x + e.y + e.z + e.w;
    s = warp_sum(s);
    if ((tid & 31) == 0) s_sum[tid >> 5] = s;
    __syncthreads();
    float tot = 0.0f;
    #pragma unroll
    for (int w = 0; w < 8; w++) tot += s_sum[w];
    float inv = 1.0f / tot;
    e.x *= inv; e.y *= inv; e.z *= inv; e.w *= inv;
    *(float4*)(rp + tid * 4) = e;
}

// ---------------- O = P @ V ----------------
__global__ void attn_av_kernel(const float* __restrict__ P, const float* __restrict__ qkv,
                               float* __restrict__ O) {
    int it = blockIdx.x, bh = blockIdx.y;
    int b = bh >> 2, h = bh & 3;
    int i0 = it * 128;
    __shared__ float p_sh[128][65];
    __shared__ float v_sh[64][16];
    int tid = threadIdx.x;
    int tx = tid & 3, ty = tid >> 2;            // d group, i group
    float acc[4][4] = {};
    for (int jt = 0; jt < 16; jt++) {
        int j0 = jt * 64;
        const float* vb = qkv + (size_t)(b * 1024 + j0) * 192 + 128 + h * 16;
        for (int f = tid; f < 1024; f += 128) {
            int r = f >> 4, d = f & 15;
            v_sh[r][d] = vb[r * 192 + d];
        }
        const float* pb = P + ((size_t)bh * 1024 + i0) * 1024 + j0;
        for (int f = tid; f < 8192; f += 128) {
            int r = f >> 6, c = f & 63;
            p_sh[r][c] = pb[(size_t)r * 1024 + c];
        }
        __syncthreads();
        #pragma unroll 4
        for (int j = 0; j < 64; j++) {
            float4 v4 = *(float4*)&v_sh[j][tx * 4];
            float vv[4] = {v4.x, v4.y, v4.z, v4.w};
            float pr[4];
            #pragma unroll
            for (int r = 0; r < 4; r++) pr[r] = p_sh[ty * 4 + r][j];
            #pragma unroll
            for (int r = 0; r < 4; r++)
                #pragma unroll
                for (int c = 0; c < 4; c++)
                    acc[r][c] = fmaf(pr[r], vv[c], acc[r][c]);
        }
        __syncthreads();
    }
    #pragma unroll
    for (int r = 0; r < 4; r++) {
        float4 o4 = make_float4(acc[r][0], acc[r][1], acc[r][2], acc[r][3]);
        *(float4*)&O[(size_t)(b * 1024 + i0 + ty * 4 + r) * 64 + h * 16 + tx * 4] = o4;
    }
}

// ---------------- elementwise stages ----------------
__global__ void resid1_kernel(const float* __restrict__ x, const float* __restrict__ ap,
                              const float* __restrict__ bo) {
    int idx = blockIdx.x * blockDim.x + threadIdx.x;
    if (idx >= ROWS * DD) return;
    g_x1[idx] = 2.0f * x[idx] + ap[idx] + bo[idx & 63];
}
__global__ void convsilu_kernel(const float* __restrict__ convw, const float* __restrict__ convb) {
    int idx = blockIdx.x * blockDim.x + threadIdx.x;
    if (idx >= ROWS * DI) return;
    int d = idx & 127, t = (idx >> 7) & 1023, b = idx >> 17;
    float acc = convb[d];
    #pragma unroll
    for (int k = 0; k < 4; k++) {
        int s = t + k - 3;
        if (s >= 0) acc = fmaf(g_xz[(size_t)((b << 10) + s) * 256 + d], convw[d * 4 + k], acc);
    }
    g_u[idx] = acc * sigmoid_f(acc);
}
__global__ void dtprep_kernel(const float* __restrict__ Wdt, const float* __restrict__ bdt) {
    int idx = blockIdx.x * blockDim.x + threadIdx.x;
    if (idx >= ROWS * DI) return;
    int d = idx & 127, bt = idx >> 7;
    float x = bdt[d];
    #pragma unroll
    for (int r = 0; r < 4; r++) x = fmaf(g_xdb[(size_t)bt * 132 + r], Wdt[r * 128 + d], x);
    g_dt[idx] = (x > 20.0f) ? x : log1pf(fast_exp(x));
}
__global__ void scan_kernel(const float* __restrict__ Alog) {
    int w = (blockIdx.x * blockDim.x + threadIdx.x) >> 5;
    int lane = threadIdx.x & 31;
    int b = w >> 7, d = w & 127;
    float A0 = -__expf(Alog[d * 64 + lane]);
    float A1 = -__expf(Alog[d * 64 + lane + 32]);
    float h0 = 0.0f, h1 = 0.0f;
    const float* dtp = g_dt + (size_t)b * 1024 * 128 + d;
    const float* up  = g_u  + (size_t)b * 1024 * 128 + d;
    const float* xp  = g_xdb + (size_t)b * 1024 * 132;
    float* yp = g_y + (size_t)b * 1024 * 128 + d;
    #pragma unroll 4
    for (int t = 0; t < 1024; t++) {
        float dtv = dtp[t << 7];
        float uv  = up[t << 7];
        float B0 = xp[t * 132 + 4 + lane],  B1 = xp[t * 132 + 36 + lane];
        float C0 = xp[t * 132 + 68 + lane], C1 = xp[t * 132 + 100 + lane];
        float du = dtv * uv;
        h0 = fmaf(h0, __expf(dtv * A0), du * B0);
        h1 = fmaf(h1, __expf(dtv * A1), du * B1);
        float p = fmaf(h0, C0, h1 * C1);
        p = warp_sum(p);
        if (lane == 0) yp[t << 7] = p;
    }
}
__global__ void ymod_kernel(const float* __restrict__ Dm) {
    int idx = blockIdx.x * blockDim.x + threadIdx.x;
    if (idx >= ROWS * DI) return;
    int d = idx & 127, bt = idx >> 7;
    float z = g_xz[(size_t)bt * 256 + 128 + d];
    g_ym[idx] = (g_y[idx] + g_u[idx] * Dm[d]) * (z * sigmoid_f(z));
}
__global__ void leakyrms_kernel(const float* __restrict__ gamma) {
    int gidx = blockIdx.x * blockDim.x + threadIdx.x;
    if (gidx >= ROWS * 4) return;
    int bt = gidx >> 2, g = gidx & 3;
    size_t base = (size_t)bt * 64 + g * 16;
    float v[16], ss = 0.0f;
    #pragma unroll
    for (int k = 0; k < 16; k++) {
        float x = g_mraw[base + k];
        x = (x >= 0.0f) ? x : 0.01f * x;
        v[k] = x; ss = fmaf(x, x, ss);
    }
    float rms = sqrtf(ss) * 0.25f;
    float sc = 1.0f / (rms + 1e-5f);
    #pragma unroll
    for (int k = 0; k < 16; k++) g_mg[base + k] = v[k] * sc * gamma[g * 16 + k];
}
__global__ void im2col1_kernel() {
    int idx = blockIdx.x * blockDim.x + threadIdx.x;
    if (idx >= ROWS1 * 256) return;
    int row = idx >> 8, c = idx & 255;
    int kt = c >> 6, ci = c & 63;
    int b = row / 1027, t = row - b * 1027;
    int s = t + kt - 3;
    g_A1[idx] = (s >= 0 && s < 1024) ? g_mg[(size_t)((b << 10) + s) * 64 + ci] : 0.0f;
}
__global__ void gate_kernel(const float* __restrict__ c1b) {
    int idx = blockIdx.x * blockDim.x + threadIdx.x;
    if (idx >= ROWS1 * 256) return;
    int row = idx >> 8, c = idx & 255;
    float a = g_xc1[(size_t)row * 512 + c] + c1b[c];
    float g = g_xc1[(size_t)row * 512 + 256 + c] + c1b[256 + c];
    g_h1[idx] = a * (g * sigmoid_f(g));
}
__global__ void im2col2_kernel() {
    int idx = blockIdx.x * blockDim.x + threadIdx.x;
    if (idx >= ROWS * 1024) return;
    int row = idx >> 10, c = idx & 1023;
    int ci = c >> 2, j = c & 3;
    int b = row >> 10, s = row & 1023;
    g_A2[idx] = g_h1[((size_t)b * 1027 + (s + 3 - j)) * 256 + ci];
}
__global__ void final_kernel(const float* __restrict__ d1b, const float* __restrict__ w,
                             const float* __restrict__ bb, float* __restrict__ out) {
    int warp = (blockIdx.x * blockDim.x + threadIdx.x) >> 5;
    int lane = threadIdx.x & 31;
    if (warp >= ROWS) return;
    size_t base = (size_t)warp * 64;
    float v0 = g_x1[base + lane]      + g_mg[base + lane]      + 0.5f * (g_ff[base + lane]      + d1b[lane]);
    float v1 = g_x1[base + lane + 32] + g_mg[base + lane + 32] + 0.5f * (g_ff[base + lane + 32] + d1b[lane + 32]);
    float mean = warp_sum(v0 + v1) * (1.0f / 64.0f);
    float d0 = v0 - mean, d1 = v1 - mean;
    float var = warp_sum(d0 * d0 + d1 * d1) * (1.0f / 64.0f);
    float inv = rsqrtf(var + 1e-5f);
    out[base + lane]      = d0 * inv * w[lane]      + bb[lane];
    out[base + lane + 32] = d1 * inv * w[lane + 32] + bb[lane + 32];
}

// ---------------- launch ----------------
static void* dev_ptr(const void* sym) { void* p = nullptr; cudaGetSymbolAddress(&p, sym); return p; }

extern "C" void kernel_launch(void* const* d_in, const int* in_sizes, int n_in,
                              void* d_out, int out_size) {
    const float* x      = (const float*)d_in[0];
    const void*  dmask  = d_in[1];
    const float* ln1w   = (const float*)d_in[2];
    const float* ln1b   = (const float*)d_in[3];
    const float* Wq     = (const float*)d_in[4];
    const float* Wkv    = (const float*)d_in[5];
    const float* Wo     = (const float*)d_in[6];
    const float* bo     = (const float*)d_in[7];
    const float* relemb = (const float*)d_in[8];
    const float* ln2w   = (const float*)d_in[9];
    const float* ln2b   = (const float*)d_in[10];
    const float* Win    = (const float*)d_in[11];
    const float* convw  = (const float*)d_in[12];
    const float* convb  = (const float*)d_in[13];
    const float* Wxproj = (const float*)d_in[14];
    const float* Wdt    = (const float*)d_in[15];
    const float* bdt    = (const float*)d_in[16];
    const float* Alog   = (const float*)d_in[17];
    const float* Dm     = (const float*)d_in[18];
    const float* Wout   = (const float*)d_in[19];
    const float* gamma  = (const float*)d_in[20];
    const float* c1w    = (const float*)d_in[21];
    const float* c1b    = (const float*)d_in[22];
    const float* d1w    = (const float*)d_in[23];
    const float* d1b    = (const float*)d_in[24];
    const float* ln3w   = (const float*)d_in[25];
    const float* ln3b   = (const float*)d_in[26];
    float* out = (float*)d_out;

    float* p_xt    = (float*)dev_ptr(g_xt);
    float* p_wqkv  = (float*)dev_ptr(g_wqkv);
    float* p_qkv   = (float*)dev_ptr(g_qkv);
    float* p_S     = (float*)dev_ptr(g_S);
    float* p_O     = (float*)dev_ptr(g_O);
    float* p_attnp = (float*)dev_ptr(g_attnp);
    float* p_x1    = (float*)dev_ptr(g_x1);
    float* p_xt2   = (float*)dev_ptr(g_xt2);
    float* p_xz    = (float*)dev_ptr(g_xz);
    float* p_u     = (float*)dev_ptr(g_u);
    float* p_xdb   = (float*)dev_ptr(g_xdb);
    float* p_ym    = (float*)dev_ptr(g_ym);
    float* p_mraw  = (float*)dev_ptr(g_mraw);
    float* p_B1    = (float*)dev_ptr(g_B1);
    float* p_A1    = (float*)dev_ptr(g_A1);
    float* p_xc1   = (float*)dev_ptr(g_xc1);
    float* p_B2    = (float*)dev_ptr(g_B2);
    float* p_A2    = (float*)dev_ptr(g_A2);
    float* p_ff    = (float*)dev_ptr(g_ff);

    // 0: mask dtype sniff
    maskmode_kernel<<<1, 256>>>((const unsigned int*)dmask);

    // 1: LN1
    ln_kernel<<<1024, 256>>>(x, ln1w, ln1b, p_xt, ROWS);

    // 2: QKV projection
    build_wqkv<<<(64 * 192 + 255) / 256, 256>>>(Wq, Wkv);
    gemm_kernel<<<dim3(3, 128), 256>>>(p_xt, p_wqkv, p_qkv, ROWS, 192, 64);

    // 3: attention
    attn_scores_kernel<<<dim3(16, 16, BH), 256>>>(p_qkv, relemb, dmask);
    softmax_kernel<<<BH * N1, 256>>>(p_S);
    attn_av_kernel<<<dim3(8, BH), 128>>>(p_S, p_qkv, p_O);
    gemm_kernel<<<dim3(1, 128), 256>>>(p_O, Wo, p_attnp, ROWS, 64, 64);
    resid1_kernel<<<(ROWS * DD + 255) / 256, 256>>>(x, p_attnp, bo);

    // 4: LN2 + Mamba
    ln_kernel<<<1024, 256>>>(p_x1, ln2w, ln2b, p_xt2, ROWS);
    gemm_kernel<<<dim3(4, 128), 256>>>(p_xt2, Win, p_xz, ROWS, 256, 64);
    convsilu_kernel<<<(ROWS * DI + 255) / 256, 256>>>(convw, convb);
    gemm_kernel<<<dim3(3, 128), 256>>>(p_u, Wxproj, p_xdb, ROWS, 132, DI);
    dtprep_kernel<<<(ROWS * DI + 255) / 256, 256>>>(Wdt, bdt);
    scan_kernel<<<128, 256>>>(Alog);
    ymod_kernel<<<(ROWS * DI + 255) / 256, 256>>>(Dm);
    gemm_kernel<<<dim3(1, 128), 256>>>(p_ym, Wout, p_mraw, ROWS, 64, DI);
    leakyrms_kernel<<<128, 256>>>(gamma);

    // 5: FF (conv1 -> gate -> conv2) via im2col GEMMs
    build_b1<<<(256 * 512 + 255) / 256, 256>>>(c1w);
    im2col1_kernel<<<(ROWS1 * 256 + 255) / 256, 256>>>();
    gemm_kernel<<<dim3(8, 129), 256>>>(p_A1, p_B1, p_xc1, ROWS1, 512, 256);
    gate_kernel<<<(ROWS1 * 256 + 255) / 256, 256>>>(c1b);
    build_b2<<<(1024 * 64 + 255) / 256, 256>>>(d1w);
    im2col2_kernel<<<(ROWS * 1024 + 255) / 256, 256>>>();
    gemm_kernel<<<dim3(1, 128), 256>>>(p_A2, p_B2, p_ff, ROWS, 64, 1024);

    // 6: final residual + LN3
    final_kernel<<<1024, 256>>>(d1b, ln3w, ln3b, out);

    (void)in_sizes; (void)n_in; (void)out_size;
}

// round 6
// speedup vs baseline: 1.1492x; 1.1492x over previous
#include <cuda_runtime.h>
#include <cstdint>
#include <cstdio>

// ---------------- problem dims ----------------
#define B8    8
#define N1    1024
#define DD    64
#define HH    4
#define DHH   16
#define DI    128
#define DS    64
#define ROWS  (B8*N1)          // 8192
#define BH    (B8*HH)          // 32
#define T1    1027             // conv1 output length
#define ROWS1 (B8*T1)          // 8216

// ---------------- scratch (static device globals; no allocation) ----------------
__device__ float g_xt   [ROWS*DD];
__device__ float g_wqkv [64*192];
__device__ float g_qkv  [ROWS*192];
__device__ float g_S    [33554432];     // (b,h,i,j) exp'd scores
__device__ float g_rowsum[BH*N1];
__device__ float g_O    [ROWS*DD];      // attention output (b,i, h*16+d)
__device__ float g_attnp[ROWS*DD];
__device__ float g_x1   [ROWS*DD];
__device__ float g_xt2  [ROWS*DD];
__device__ float g_xz   [ROWS*256];
__device__ float g_u    [ROWS*DI];
__device__ float g_xdb  [ROWS*132];
__device__ float g_dt   [ROWS*DI];
__device__ float g_y    [ROWS*DI];
__device__ float g_ym   [ROWS*DI];
__device__ float g_mraw [ROWS*DD];
__device__ float g_mg   [ROWS*DD];
__device__ float g_B1   [256*512];
__device__ float g_xc1  [ROWS1*512];
__device__ float g_h1   [ROWS1*256];
__device__ float g_B2   [1024*64];
__device__ float g_ff   [ROWS*DD];
__device__ int   g_mask_mode;

// ---------------- helpers ----------------
__device__ __forceinline__ float fast_exp(float x) {
    float t = x * 1.4426950408889634f;
    t = fminf(fmaxf(t, -126.0f), 126.0f);
    float fi = floorf(t);
    float f  = t - fi;
    float p = 0.0018775767f;
    p = fmaf(p, f, 0.0089893397f);
    p = fmaf(p, f, 0.055826318f);
    p = fmaf(p, f, 0.24015361f);
    p = fmaf(p, f, 0.69315308f);
    p = fmaf(p, f, 0.99999994f);
    return p * __int_as_float(((int)fi + 127) << 23);
}
__device__ __forceinline__ float sigmoid_f(float x) { return 1.0f / (1.0f + fast_exp(-x)); }
__device__ __forceinline__ float warp_sum(float v) {
    #pragma unroll
    for (int o = 16; o > 0; o >>= 1) v += __shfl_xor_sync(0xFFFFFFFFu, v, o);
    return v;
}

// ---------------- mask dtype sniffer ----------------
__global__ void maskmode_kernel(const unsigned int* __restrict__ m) {
    __shared__ int cf, co;
    if (threadIdx.x == 0) { cf = 0; co = 0; }
    __syncthreads();
    int lf = 0, lo = 0;
    for (int k = 0; k < 16; k++) {
        unsigned w = m[threadIdx.x + k * 256];
        if (w == 0x3F800000u) lf++;
        else if (w != 0u && w != 1u) lo++;
    }
    atomicAdd(&cf, lf); atomicAdd(&co, lo);
    __syncthreads();
    if (threadIdx.x == 0)
        g_mask_mode = (cf > 32) ? 0 : ((co > 32) ? 2 : 1);  // 0=f32, 1=i32, 2=u8
}

__global__ void zerosum_kernel() {
    g_rowsum[blockIdx.x * 256 + threadIdx.x] = 0.0f;
}

// ---------------- layernorm (warp per row of 64) ----------------
__global__ void ln_kernel(const float* __restrict__ x, const float* __restrict__ w,
                          const float* __restrict__ b, float* __restrict__ out, int rows) {
    int warp = (blockIdx.x * blockDim.x + threadIdx.x) >> 5;
    int lane = threadIdx.x & 31;
    if (warp >= rows) return;
    const float* xr = x + (size_t)warp * 64;
    float v0 = xr[lane], v1 = xr[lane + 32];
    float mean = warp_sum(v0 + v1) * (1.0f / 64.0f);
    float d0 = v0 - mean, d1 = v1 - mean;
    float var = warp_sum(d0 * d0 + d1 * d1) * (1.0f / 64.0f);
    float inv = rsqrtf(var + 1e-5f);
    float* orow = out + (size_t)warp * 64;
    orow[lane]      = d0 * inv * w[lane]      + b[lane];
    orow[lane + 32] = d1 * inv * w[lane + 32] + b[lane + 32];
}

// ---------------- tuned GEMM: C[M,N] = A[M,K] * B[K,N], 128x64 tile, 8x4 micro
// mode 0: A is row-major [M,K]
// mode 1: conv1 implicit im2col: A = g_mg [8*1024,64]; row in [0,8216): b=row/1027,
//         t=row%1027; col k: kt=k>>6, ci=k&63; src = mg[(b*1024 + t+kt-3)*64+ci] (0 if OOB)
// mode 2: conv2 implicit im2col: A = g_h1 [8216,256]; row: b=row>>10, s=row&1023;
//         col k: ci=k>>2, j=k&3; src = h1[(b*1027 + s+3-j)*256 + ci]
__global__ void gemm128_kernel(const float* __restrict__ A, const float* __restrict__ B,
                               float* __restrict__ C, int M, int N, int K, int mode) {
    __shared__ float As[16][132];
    __shared__ float Bs[16][68];
    int bm0 = blockIdx.y * 128, bn0 = blockIdx.x * 64;
    int tid = threadIdx.x;
    int tx = tid & 15, ty = tid >> 4;

    // precompute per-load-slot row info (m fixed across k-tiles)
    size_t abase[8];
    int    arowt[8];
    bool   avalid[8];
    #pragma unroll
    for (int i = 0; i < 8; i++) {
        int f = tid + i * 256;
        int m = f >> 4;
        int gm = bm0 + m;
        avalid[i] = (gm < M);
        int gmc = avalid[i] ? gm : 0;
        if (mode == 0) {
            abase[i] = (size_t)gmc * K;
            arowt[i] = 0;
        } else if (mode == 1) {
            int b = gmc / 1027;
            int t = gmc - b * 1027;
            abase[i] = (size_t)(b << 10) * 64;
            arowt[i] = t;
        } else {
            int b = gmc >> 10, s = gmc & 1023;
            abase[i] = ((size_t)b * 1027 + s) * 256;
            arowt[i] = 0;
        }
    }

    float acc[8][4] = {};
    for (int k0 = 0; k0 < K; k0 += 16) {
        #pragma unroll
        for (int i = 0; i < 8; i++) {
            int f = tid + i * 256;
            int m = f >> 4, kk = f & 15;
            int k = k0 + kk;
            float v = 0.0f;
            if (mode == 0) {
                if (avalid[i]) v = A[abase[i] + k];
            } else if (mode == 1) {
                int kt = k >> 6, ci = k & 63;
                int s = arowt[i] + kt - 3;
                if (avalid[i] && s >= 0 && s < 1024) v = A[abase[i] + (size_t)s * 64 + ci];
            } else {
                int ci = k >> 2, j = k & 3;
                if (avalid[i]) v = A[abase[i] + (size_t)(3 - j) * 256 + ci];
            }
            As[kk][m] = v;
        }
        #pragma unroll
        for (int i = 0; i < 4; i++) {
            int f = tid + i * 256;
            int kk = f >> 6, n = f & 63;
            int gn = bn0 + n;
            Bs[kk][n] = (gn < N) ? B[(size_t)(k0 + kk) * N + gn] : 0.0f;
        }
        __syncthreads();
        #pragma unroll
        for (int kk = 0; kk < 16; kk++) {
            float4 a0 = *(const float4*)&As[kk][ty * 8];
            float4 a1 = *(const float4*)&As[kk][ty * 8 + 4];
            float4 b4 = *(const float4*)&Bs[kk][tx * 4];
            float av[8] = {a0.x, a0.y, a0.z, a0.w, a1.x, a1.y, a1.z, a1.w};
            float bv[4] = {b4.x, b4.y, b4.z, b4.w};
            #pragma unroll
            for (int r = 0; r < 8; r++)
                #pragma unroll
                for (int c = 0; c < 4; c++)
                    acc[r][c] = fmaf(av[r], bv[c], acc[r][c]);
        }
        __syncthreads();
    }
    #pragma unroll
    for (int r = 0; r < 8; r++) {
        int gm = bm0 + ty * 8 + r;
        if (gm < M) {
            #pragma unroll
            for (int c = 0; c < 4; c++) {
                int gn = bn0 + tx * 4 + c;
                if (gn < N) C[(size_t)gm * N + gn] = acc[r][c];
            }
        }
    }
}

// ---------------- small builders ----------------
__global__ void build_wqkv(const float* __restrict__ Wq, const float* __restrict__ Wkv) {
    int idx = blockIdx.x * blockDim.x + threadIdx.x;
    if (idx >= 64 * 192) return;
    int k = idx / 192, c = idx % 192;
    g_wqkv[idx] = (c < 64) ? Wq[k * 64 + c] : Wkv[k * 128 + (c - 64)];
}
__global__ void build_b1(const float* __restrict__ c1w) {
    int idx = blockIdx.x * blockDim.x + threadIdx.x;
    if (idx >= 256 * 512) return;
    int r = idx >> 9, o = idx & 511;
    int kt = r >> 6, ci = r & 63;
    g_B1[idx] = c1w[o * 256 + ci * 4 + kt];
}
__global__ void build_b2(const float* __restrict__ d1w) {
    int idx = blockIdx.x * blockDim.x + threadIdx.x;
    if (idx >= 1024 * 64) return;
    int r = idx >> 6, co = idx & 63;
    int ci = r >> 2, j = r & 3;
    g_B2[idx] = d1w[ci * 256 + co * 4 + j];
}

// ---------------- attention scores + fused exp + row-sum atomics ----------------
__global__ void attn_scores_kernel(const float* __restrict__ qkv,
                                   const float* __restrict__ relemb,
                                   const void* __restrict__ mask) {
    int jt = blockIdx.x, it = blockIdx.y, bh = blockIdx.z;
    int b = bh >> 2, h = bh & 3;
    int i0 = it * 64, j0 = jt * 64;
    __shared__ float q_sh[64][17];
    __shared__ float k_sh[64][17];
    __shared__ float rel_sh[127][17];
    int tid = threadIdx.x;
    const float* qbase = qkv + (size_t)(b * 1024 + i0) * 192 + h * 16;
    const float* kbase = qkv + (size_t)(b * 1024 + j0) * 192 + 64 + h * 16;
    for (int f = tid; f < 1024; f += 256) {
        int r = f >> 4, d = f & 15;
        q_sh[r][d] = qbase[r * 192 + d];
        k_sh[r][d] = kbase[r * 192 + d];
    }
    int pbase = i0 - j0 + 449;
    for (int f = tid; f < 127 * 16; f += 256) {
        int r = f >> 4, d = f & 15;
        int p = pbase + r;
        p = min(max(p, 0), 1024);
        rel_sh[r][d] = relemb[p * 16 + d];
    }
    __syncthreads();
    int tx = tid & 15, ty = tid >> 4;
    int lbase = (ty - tx) * 4 + 60;
    float acc[4][4] = {};
    #pragma unroll
    for (int d = 0; d < 16; d++) {
        float aq[4], bk[4], rl[7];
        #pragma unroll
        for (int r = 0; r < 4; r++) aq[r] = q_sh[ty * 4 + r][d];
        #pragma unroll
        for (int c = 0; c < 4; c++) bk[c] = k_sh[tx * 4 + c][d];
        #pragma unroll
        for (int m = 0; m < 7; m++) rl[m] = rel_sh[lbase + m][d];
        #pragma unroll
        for (int r = 0; r < 4; r++)
            #pragma unroll
            for (int c = 0; c < 4; c++)
                acc[r][c] = fmaf(aq[r], bk[c] + rl[r - c + 3], acc[r][c]);
    }
    int mode = g_mask_mode;
    size_t base = ((size_t)bh * 1024 + i0) * 1024 + j0;
    float rsum[4];
    #pragma unroll
    for (int r = 0; r < 4; r++) {
        size_t rowo = base + (size_t)(ty * 4 + r) * 1024 + tx * 4;
        float4 out;
        float s4 = 0.0f;
        #pragma unroll
        for (int c = 0; c < 4; c++) {
            float s = acc[r][c] * 0.25f;
            size_t mi = rowo + c;
            bool msk;
            if (mode == 0)      msk = ((const float*)mask)[mi] != 0.0f;
            else if (mode == 1) msk = ((const int*)mask)[mi] != 0;
            else                msk = ((const unsigned char*)mask)[mi] != 0;
            float e = msk ? 0.0f : fast_exp(s);   // scores are O(4): no max-sub needed
            (&out.x)[c] = e;
            s4 += e;
        }
        *(float4*)(g_S + rowo) = out;
        rsum[r] = s4;
    }
    // reduce row sums over tx (16 lanes within each half-warp), then atomics
    #pragma unroll
    for (int r = 0; r < 4; r++) {
        float v = rsum[r];
        v += __shfl_xor_sync(0xFFFFFFFFu, v, 1);
        v += __shfl_xor_sync(0xFFFFFFFFu, v, 2);
        v += __shfl_xor_sync(0xFFFFFFFFu, v, 4);
        v += __shfl_xor_sync(0xFFFFFFFFu, v, 8);
        if (tx == 0)
            atomicAdd(&g_rowsum[bh * 1024 + i0 + ty * 4 + r], v);
    }
}

// ---------------- O = (P @ V) / rowsum ----------------
__global__ void attn_av_kernel(const float* __restrict__ P, const float* __restrict__ qkv,
                               float* __restrict__ O) {
    int it = blockIdx.x, bh = blockIdx.y;
    int b = bh >> 2, h = bh & 3;
    int i0 = it * 64;
    __shared__ float p_sh[64][68];
    __shared__ float vt_sh[16][68];
    int tid = threadIdx.x;
    int tx = tid & 15, ty = tid >> 4;
    float acc[4] = {};
    for (int jt = 0; jt < 16; jt++) {
        int j0 = jt * 64;
        const float* pb = P + ((size_t)bh * 1024 + i0) * 1024 + j0;
        #pragma unroll
        for (int i = 0; i < 4; i++) {
            int f = tid + i * 256;             // 1024 float4 groups
            int r = f >> 4, c4 = f & 15;
            *(float4*)&p_sh[r][c4 * 4] = *(const float4*)(pb + (size_t)r * 1024 + c4 * 4);
        }
        const float* vb = qkv + (size_t)(b * 1024 + j0) * 192 + 128 + h * 16;
        #pragma unroll
        for (int i = 0; i < 4; i++) {
            int f = tid + i * 256;
            int j = f >> 4, d = f & 15;
            vt_sh[d][j] = vb[j * 192 + d];
        }
        __syncthreads();
        #pragma unroll
        for (int j4 = 0; j4 < 16; j4++) {
            float4 v4 = *(const float4*)&vt_sh[tx][j4 * 4];
            #pragma unroll
            for (int r = 0; r < 4; r++) {
                float4 p4 = *(const float4*)&p_sh[ty * 4 + r][j4 * 4];
                acc[r] = fmaf(p4.x, v4.x, acc[r]);
                acc[r] = fmaf(p4.y, v4.y, acc[r]);
                acc[r] = fmaf(p4.z, v4.z, acc[r]);
                acc[r] = fmaf(p4.w, v4.w, acc[r]);
            }
        }
        __syncthreads();
    }
    #pragma unroll
    for (int r = 0; r < 4; r++) {
        int i = i0 + ty * 4 + r;
        float inv = 1.0f / g_rowsum[bh * 1024 + i];
        O[(size_t)(b * 1024 + i) * 64 + h * 16 + tx] = acc[r] * inv;
    }
}

// ---------------- elementwise stages ----------------
__global__ void resid1_kernel(const float* __restrict__ x, const float* __restrict__ ap,
                              const float* __restrict__ bo) {
    int idx = blockIdx.x * blockDim.x + threadIdx.x;
    if (idx >= ROWS * DD) return;
    g_x1[idx] = 2.0f * x[idx] + ap[idx] + bo[idx & 63];
}
__global__ void convsilu_kernel(const float* __restrict__ convw, const float* __restrict__ convb) {
    int idx = blockIdx.x * blockDim.x + threadIdx.x;
    if (idx >= ROWS * DI) return;
    int d = idx & 127, t = (idx >> 7) & 1023, b = idx >> 17;
    float acc = convb[d];
    #pragma unroll
    for (int k = 0; k < 4; k++) {
        int s = t + k - 3;
        if (s >= 0) acc = fmaf(g_xz[(size_t)((b << 10) + s) * 256 + d], convw[d * 4 + k], acc);
    }
    g_u[idx] = acc * sigmoid_f(acc);
}
__global__ void dtprep_kernel(const float* __restrict__ Wdt, const float* __restrict__ bdt) {
    int idx = blockIdx.x * blockDim.x + threadIdx.x;
    if (idx >= ROWS * DI) return;
    int d = idx & 127, bt = idx >> 7;
    float x = bdt[d];
    #pragma unroll
    for (int r = 0; r < 4; r++) x = fmaf(g_xdb[(size_t)bt * 132 + r], Wdt[r * 128 + d], x);
    g_dt[idx] = (x > 20.0f) ? x : log1pf(fast_exp(x));
}
__global__ void scan_kernel(const float* __restrict__ Alog) {
    int w = (blockIdx.x * blockDim.x + threadIdx.x) >> 5;
    int lane = threadIdx.x & 31;
    int b = w >> 7, d = w & 127;
    float A0 = -__expf(Alog[d * 64 + lane]);
    float A1 = -__expf(Alog[d * 64 + lane + 32]);
    float h0 = 0.0f, h1 = 0.0f;
    const float* dtp = g_dt + (size_t)b * 1024 * 128 + d;
    const float* up  = g_u  + (size_t)b * 1024 * 128 + d;
    const float* xp  = g_xdb + (size_t)b * 1024 * 132;
    float* yp = g_y + (size_t)b * 1024 * 128 + d;
    #pragma unroll 4
    for (int t = 0; t < 1024; t++) {
        float dtv = dtp[t << 7];
        float uv  = up[t << 7];
        float B0 = xp[t * 132 + 4 + lane],  B1 = xp[t * 132 + 36 + lane];
        float C0 = xp[t * 132 + 68 + lane], C1 = xp[t * 132 + 100 + lane];
        float du = dtv * uv;
        h0 = fmaf(h0, __expf(dtv * A0), du * B0);
        h1 = fmaf(h1, __expf(dtv * A1), du * B1);
        float p = fmaf(h0, C0, h1 * C1);
        p = warp_sum(p);
        if (lane == 0) yp[t << 7] = p;
    }
}
__global__ void ymod_kernel(const float* __restrict__ Dm) {
    int idx = blockIdx.x * blockDim.x + threadIdx.x;
    if (idx >= ROWS * DI) return;
    int d = idx & 127, bt = idx >> 7;
    float z = g_xz[(size_t)bt * 256 + 128 + d];
    g_ym[idx] = (g_y[idx] + g_u[idx] * Dm[d]) * (z * sigmoid_f(z));
}
__global__ void leakyrms_kernel(const float* __restrict__ gamma) {
    int gidx = blockIdx.x * blockDim.x + threadIdx.x;
    if (gidx >= ROWS * 4) return;
    int bt = gidx >> 2, g = gidx & 3;
    size_t base = (size_t)bt * 64 + g * 16;
    float v[16], ss = 0.0f;
    #pragma unroll
    for (int k = 0; k < 16; k++) {
        float x = g_mraw[base + k];
        x = (x >= 0.0f) ? x : 0.01f * x;
        v[k] = x; ss = fmaf(x, x, ss);
    }
    float rms = sqrtf(ss) * 0.25f;
    float sc = 1.0f / (rms + 1e-5f);
    #pragma unroll
    for (int k = 0; k < 16; k++) g_mg[base + k] = v[k] * sc * gamma[g * 16 + k];
}
__global__ void gate_kernel(const float* __restrict__ c1b) {
    int idx = blockIdx.x * blockDim.x + threadIdx.x;
    if (idx >= ROWS1 * 256) return;
    int row = idx >> 8, c = idx & 255;
    float a = g_xc1[(size_t)row * 512 + c] + c1b[c];
    float g = g_xc1[(size_t)row * 512 + 256 + c] + c1b[256 + c];
    g_h1[idx] = a * (g * sigmoid_f(g));
}
__global__ void final_kernel(const float* __restrict__ d1b, const float* __restrict__ w,
                             const float* __restrict__ bb, float* __restrict__ out) {
    int warp = (blockIdx.x * blockDim.x + threadIdx.x) >> 5;
    int lane = threadIdx.x & 31;
    if (warp >= ROWS) return;
    size_t base = (size_t)warp * 64;
    float v0 = g_x1[base + lane]      + g_mg[base + lane]      + 0.5f * (g_ff[base + lane]      + d1b[lane]);
    float v1 = g_x1[base + lane + 32] + g_mg[base + lane + 32] + 0.5f * (g_ff[base + lane + 32] + d1b[lane + 32]);
    float mean = warp_sum(v0 + v1) * (1.0f / 64.0f);
    float d0 = v0 - mean, d1 = v1 - mean;
    float var = warp_sum(d0 * d0 + d1 * d1) * (1.0f / 64.0f);
    float inv = rsqrtf(var + 1e-5f);
    out[base + lane]      = d0 * inv * w[lane]      + bb[lane];
    out[base + lane + 32] = d1 * inv * w[lane + 32] + bb[lane + 32];
}

// ---------------- launch ----------------
static void* dev_ptr(const void* sym) { void* p = nullptr; cudaGetSymbolAddress(&p, sym); return p; }

extern "C" void kernel_launch(void* const* d_in, const int* in_sizes, int n_in,
                              void* d_out, int out_size) {
    const float* x      = (const float*)d_in[0];
    const void*  dmask  = d_in[1];
    const float* ln1w   = (const float*)d_in[2];
    const float* ln1b   = (const float*)d_in[3];
    const float* Wq     = (const float*)d_in[4];
    const float* Wkv    = (const float*)d_in[5];
    const float* Wo     = (const float*)d_in[6];
    const float* bo     = (const float*)d_in[7];
    const float* relemb = (const float*)d_in[8];
    const float* ln2w   = (const float*)d_in[9];
    const float* ln2b   = (const float*)d_in[10];
    const float* Win    = (const float*)d_in[11];
    const float* convw  = (const float*)d_in[12];
    const float* convb  = (const float*)d_in[13];
    const float* Wxproj = (const float*)d_in[14];
    const float* Wdt    = (const float*)d_in[15];
    const float* bdt    = (const float*)d_in[16];
    const float* Alog   = (const float*)d_in[17];
    const float* Dm     = (const float*)d_in[18];
    const float* Wout   = (const float*)d_in[19];
    const float* gamma  = (const float*)d_in[20];
    const float* c1w    = (const float*)d_in[21];
    const float* c1b    = (const float*)d_in[22];
    const float* d1w    = (const float*)d_in[23];
    const float* d1b    = (const float*)d_in[24];
    const float* ln3w   = (const float*)d_in[25];
    const float* ln3b   = (const float*)d_in[26];
    float* out = (float*)d_out;

    float* p_xt    = (float*)dev_ptr(g_xt);
    float* p_wqkv  = (float*)dev_ptr(g_wqkv);
    float* p_qkv   = (float*)dev_ptr(g_qkv);
    float* p_S     = (float*)dev_ptr(g_S);
    float* p_O     = (float*)dev_ptr(g_O);
    float* p_attnp = (float*)dev_ptr(g_attnp);
    float* p_x1    = (float*)dev_ptr(g_x1);
    float* p_xt2   = (float*)dev_ptr(g_xt2);
    float* p_xz    = (float*)dev_ptr(g_xz);
    float* p_u     = (float*)dev_ptr(g_u);
    float* p_xdb   = (float*)dev_ptr(g_xdb);
    float* p_ym    = (float*)dev_ptr(g_ym);
    float* p_mraw  = (float*)dev_ptr(g_mraw);
    float* p_mg    = (float*)dev_ptr(g_mg);
    float* p_B1    = (float*)dev_ptr(g_B1);
    float* p_xc1   = (float*)dev_ptr(g_xc1);
    float* p_h1    = (float*)dev_ptr(g_h1);
    float* p_B2    = (float*)dev_ptr(g_B2);
    float* p_ff    = (float*)dev_ptr(g_ff);

    // 0: mask dtype sniff + rowsum zero
    maskmode_kernel<<<1, 256>>>((const unsigned int*)dmask);
    zerosum_kernel<<<BH * N1 / 256, 256>>>();

    // 1: LN1
    ln_kernel<<<1024, 256>>>(x, ln1w, ln1b, p_xt, ROWS);

    // 2: QKV projection
    build_wqkv<<<(64 * 192 + 255) / 256, 256>>>(Wq, Wkv);
    gemm128_kernel<<<dim3(3, 64), 256>>>(p_xt, p_wqkv, p_qkv, ROWS, 192, 64, 0);

    // 3: attention (fused exp+rowsum; no separate softmax pass)
    attn_scores_kernel<<<dim3(16, 16, BH), 256>>>(p_qkv, relemb, dmask);
    attn_av_kernel<<<dim3(16, BH), 256>>>(p_S, p_qkv, p_O);
    gemm128_kernel<<<dim3(1, 64), 256>>>(p_O, Wo, p_attnp, ROWS, 64, 64, 0);
    resid1_kernel<<<(ROWS * DD + 255) / 256, 256>>>(x, p_attnp, bo);

    // 4: LN2 + Mamba
    ln_kernel<<<1024, 256>>>(p_x1, ln2w, ln2b, p_xt2, ROWS);
    gemm128_kernel<<<dim3(4, 64), 256>>>(p_xt2, Win, p_xz, ROWS, 256, 64, 0);
    convsilu_kernel<<<(ROWS * DI + 255) / 256, 256>>>(convw, convb);
    gemm128_kernel<<<dim3(3, 64), 256>>>(p_u, Wxproj, p_xdb, ROWS, 132, DI, 0);
    dtprep_kernel<<<(ROWS * DI + 255) / 256, 256>>>(Wdt, bdt);
    scan_kernel<<<128, 256>>>(Alog);
    ymod_kernel<<<(ROWS * DI + 255) / 256, 256>>>(Dm);
    gemm128_kernel<<<dim3(1, 64), 256>>>(p_ym, Wout, p_mraw, ROWS, 64, DI, 0);
    leakyrms_kernel<<<128, 256>>>(gamma);

    // 5: FF (conv1 -> gate -> conv2) via implicit-im2col GEMMs
    build_b1<<<(256 * 512 + 255) / 256, 256>>>(c1w);
    gemm128_kernel<<<dim3(8, 65), 256>>>(p_mg, p_B1, p_xc1, ROWS1, 512, 256, 1);
    gate_kernel<<<(ROWS1 * 256 + 255) / 256, 256>>>(c1b);
    build_b2<<<(1024 * 64 + 255) / 256, 256>>>(d1w);
    gemm128_kernel<<<dim3(1, 64), 256>>>(p_h1, p_B2, p_ff, ROWS, 64, 1024, 2);

    // 6: final residual + LN3
    final_kernel<<<1024, 256>>>(d1b, ln3w, ln3b, out);

    (void)in_sizes; (void)n_in; (void)out_size;
}